// round 1
// baseline (speedup 1.0000x reference)
#include <cuda_runtime.h>
#include <cuda_bf16.h>
#include <math.h>

// Problem constants
#define B_  2
#define S_  1024
#define D_  1024
#define H_  16
#define HD_ 64
#define L_  8
#define FF_ 4096
#define V_  50257
#define EPS_ 1e-5f
#define NTOK (B_ * S_)          // 2048 rows

// ---------------------------------------------------------------------------
// Scratch buffers (static device globals — allocation-free)
// ---------------------------------------------------------------------------
__device__ float g_x[NTOK * D_];                         // residual stream   8 MB
__device__ float g_h[NTOK * D_];                         // ln output         8 MB
__device__ float g_qkv[NTOK * 3 * D_];                   // qkv proj         24 MB
__device__ float g_scores[(size_t)B_ * H_ * S_ * S_];    // attn scores     128 MB
__device__ float g_attn[NTOK * D_];                      // attn output      8 MB
__device__ float g_ffh[NTOK * FF_];                      // mlp hidden      32 MB

// ---------------------------------------------------------------------------
// Embedding: x[b,s,:] = tok_emb[idx[b,s],:] + pos_emb[s,:]
// ---------------------------------------------------------------------------
__global__ void embed_kernel(const int* __restrict__ idx,
                             const float* __restrict__ tok,
                             const float* __restrict__ pos)
{
    int row = blockIdx.x;            // b*S + s
    int s = row % S_;
    int t = idx[row];
    const float* te = tok + (size_t)t * D_;
    const float* pe = pos + (size_t)s * D_;
    float* o = g_x + (size_t)row * D_;
    for (int c = threadIdx.x; c < D_; c += blockDim.x)
        o[c] = te[c] + pe[c];
}

// ---------------------------------------------------------------------------
// LayerNorm, one block per row of D_=1024
// ---------------------------------------------------------------------------
__global__ void __launch_bounds__(256) ln_kernel(const float* __restrict__ in,
                                                 float* __restrict__ out,
                                                 const float* __restrict__ sc,
                                                 const float* __restrict__ bi)
{
    int row = blockIdx.x;
    const float* x = in + (size_t)row * D_;
    float* y = out + (size_t)row * D_;
    __shared__ float red[256];
    int tid = threadIdx.x;

    float s = 0.f;
    for (int c = tid; c < D_; c += 256) s += x[c];
    red[tid] = s; __syncthreads();
    for (int o = 128; o > 0; o >>= 1) {
        if (tid < o) red[tid] += red[tid + o];
        __syncthreads();
    }
    float mu = red[0] * (1.f / D_);
    __syncthreads();

    float v = 0.f;
    for (int c = tid; c < D_; c += 256) { float d = x[c] - mu; v += d * d; }
    red[tid] = v; __syncthreads();
    for (int o = 128; o > 0; o >>= 1) {
        if (tid < o) red[tid] += red[tid + o];
        __syncthreads();
    }
    float rstd = rsqrtf(red[0] * (1.f / D_) + EPS_);

    for (int c = tid; c < D_; c += 256)
        y[c] = (x[c] - mu) * rstd * sc[c] + bi[c];
}

// ---------------------------------------------------------------------------
// Generic SGEMM:  C[M,N] = A[M,K] * B[N,K]^T  (+bias[n]) (ReLU) (+res[M,N])
// 128x128 block tile, BK=8, 256 threads, 8x8 per thread.
// M is always a multiple of 128 here; N may be ragged (head: 50257).
// ---------------------------------------------------------------------------
__global__ void __launch_bounds__(256) gemm_kernel(
    const float* __restrict__ A, const float* __restrict__ Bw,
    const float* __restrict__ bias, const float* __restrict__ res,
    float* __restrict__ C, int M, int N, int K, int relu)
{
    __shared__ float As[8][128];
    __shared__ float Bs[8][128];

    int tid = threadIdx.x;
    int m0 = blockIdx.y * 128;
    int n0 = blockIdx.x * 128;
    int ty = tid >> 4;           // 0..15
    int tx = tid & 15;           // 0..15

    float acc[8][8];
#pragma unroll
    for (int i = 0; i < 8; i++)
#pragma unroll
        for (int j = 0; j < 8; j++) acc[i][j] = 0.f;

    int ldRow = tid >> 1;            // 0..127
    int ldCol = (tid & 1) * 4;       // 0 or 4
    const float* Aptr = A + (size_t)(m0 + ldRow) * K + ldCol;
    int bRowG = n0 + ldRow;
    bool bValid = bRowG < N;
    const float* Bptr = Bw + (size_t)(bValid ? bRowG : 0) * K + ldCol;

    for (int k0 = 0; k0 < K; k0 += 8) {
        float4 av = *(const float4*)(Aptr + k0);
        float4 bv = bValid ? *(const float4*)(Bptr + k0)
                           : make_float4(0.f, 0.f, 0.f, 0.f);
        As[ldCol + 0][ldRow] = av.x; As[ldCol + 1][ldRow] = av.y;
        As[ldCol + 2][ldRow] = av.z; As[ldCol + 3][ldRow] = av.w;
        Bs[ldCol + 0][ldRow] = bv.x; Bs[ldCol + 1][ldRow] = bv.y;
        Bs[ldCol + 2][ldRow] = bv.z; Bs[ldCol + 3][ldRow] = bv.w;
        __syncthreads();

#pragma unroll
        for (int kk = 0; kk < 8; kk++) {
            float a[8], b[8];
#pragma unroll
            for (int i = 0; i < 8; i++) a[i] = As[kk][ty * 8 + i];
#pragma unroll
            for (int j = 0; j < 8; j++) b[j] = Bs[kk][tx * 8 + j];
#pragma unroll
            for (int i = 0; i < 8; i++)
#pragma unroll
                for (int j = 0; j < 8; j++)
                    acc[i][j] = fmaf(a[i], b[j], acc[i][j]);
        }
        __syncthreads();
    }

#pragma unroll
    for (int i = 0; i < 8; i++) {
        int m = m0 + ty * 8 + i;
        if (m >= M) continue;
#pragma unroll
        for (int j = 0; j < 8; j++) {
            int n = n0 + tx * 8 + j;
            if (n >= N) continue;
            float v = acc[i][j];
            if (bias) v += bias[n];
            if (relu) v = fmaxf(v, 0.f);
            if (res)  v += res[(size_t)m * N + n];
            C[(size_t)m * N + n] = v;
        }
    }
}

// ---------------------------------------------------------------------------
// Attention scores: scores[bh,q,k] = scale * sum_d q[b,q,h,d]*k[b,k,h,d]
// q,k live in g_qkv: row (b*S+t)*3072, head h -> q at col h*192, k at h*192+64
// 64x64 tile, K=64 fully resident. Skip tiles entirely above the diagonal.
// ---------------------------------------------------------------------------
__global__ void __launch_bounds__(256) scores_kernel()
{
    int q0 = blockIdx.x * 64;
    int k0 = blockIdx.y * 64;
    if (k0 > q0 + 63) return;                 // fully masked tile
    int bh = blockIdx.z;
    int b = bh >> 4, h = bh & 15;

    __shared__ float Qs[64][65];
    __shared__ float Ks[64][65];
    int tid = threadIdx.x;

    for (int i = tid; i < 64 * 64; i += 256) {
        int r = i >> 6, c = i & 63;
        Qs[r][c] = g_qkv[(size_t)(b * S_ + q0 + r) * (3 * D_) + h * 192 + c];
        Ks[r][c] = g_qkv[(size_t)(b * S_ + k0 + r) * (3 * D_) + h * 192 + 64 + c];
    }
    __syncthreads();

    int ty = tid >> 4, tx = tid & 15;
    float acc[4][4];
#pragma unroll
    for (int i = 0; i < 4; i++)
#pragma unroll
        for (int j = 0; j < 4; j++) acc[i][j] = 0.f;

#pragma unroll 8
    for (int d = 0; d < 64; d++) {
        float a[4], bb[4];
#pragma unroll
        for (int i = 0; i < 4; i++) a[i]  = Qs[ty * 4 + i][d];
#pragma unroll
        for (int j = 0; j < 4; j++) bb[j] = Ks[tx * 4 + j][d];
#pragma unroll
        for (int i = 0; i < 4; i++)
#pragma unroll
            for (int j = 0; j < 4; j++)
                acc[i][j] = fmaf(a[i], bb[j], acc[i][j]);
    }

    const float scale = 0.125f;   // HD^-0.5
#pragma unroll
    for (int i = 0; i < 4; i++) {
        int q = q0 + ty * 4 + i;
#pragma unroll
        for (int j = 0; j < 4; j++) {
            int k = k0 + tx * 4 + j;
            g_scores[((size_t)bh * S_ + q) * S_ + k] = acc[i][j] * scale;
        }
    }
}

// ---------------------------------------------------------------------------
// Causal softmax, in place over g_scores. One block per (bh, q) row.
// Masked tail [q+1, S) is written as 0 so the P@V GEMM can run dense.
// ---------------------------------------------------------------------------
__global__ void __launch_bounds__(256) softmax_kernel()
{
    int row = blockIdx.x;          // bh*S + q
    int q = row & (S_ - 1);
    float* p = g_scores + (size_t)row * S_;
    int valid = q + 1;
    int tid = threadIdx.x;
    __shared__ float red[256];

    float m = -1e30f;
    for (int c = tid; c < valid; c += 256) m = fmaxf(m, p[c]);
    red[tid] = m; __syncthreads();
    for (int o = 128; o > 0; o >>= 1) {
        if (tid < o) red[tid] = fmaxf(red[tid], red[tid + o]);
        __syncthreads();
    }
    m = red[0]; __syncthreads();

    float s = 0.f;
    for (int c = tid; c < valid; c += 256) {
        float e = __expf(p[c] - m);
        p[c] = e;
        s += e;
    }
    red[tid] = s; __syncthreads();
    for (int o = 128; o > 0; o >>= 1) {
        if (tid < o) red[tid] += red[tid + o];
        __syncthreads();
    }
    float inv = 1.f / red[0];

    for (int c = tid; c < valid; c += 256) p[c] *= inv;
    for (int c = valid + tid; c < S_; c += 256) p[c] = 0.f;
}

// ---------------------------------------------------------------------------
// attn_out[b,q,h*64+d] = sum_k probs[bh,q,k] * v[b,k,h,d]
// v at g_qkv col h*192+128. 64(q) x 64(d) tile, K chunks of 64,
// only chunks with k0 <= q0+63 (probs are zero beyond).
// ---------------------------------------------------------------------------
__global__ void __launch_bounds__(256) attnout_kernel()
{
    int q0 = blockIdx.x * 64;
    int bh = blockIdx.y;
    int b = bh >> 4, h = bh & 15;

    __shared__ float Ps[64][65];
    __shared__ float Vs[64][65];
    int tid = threadIdx.x;
    int ty = tid >> 4, tx = tid & 15;

    float acc[4][4];
#pragma unroll
    for (int i = 0; i < 4; i++)
#pragma unroll
        for (int j = 0; j < 4; j++) acc[i][j] = 0.f;

    int nChunks = (q0 >> 6) + 1;
    for (int kc = 0; kc < nChunks; kc++) {
        int k0 = kc * 64;
        for (int i = tid; i < 64 * 64; i += 256) {
            int r = i >> 6, c = i & 63;
            Ps[r][c] = g_scores[((size_t)bh * S_ + q0 + r) * S_ + k0 + c];
            Vs[r][c] = g_qkv[(size_t)(b * S_ + k0 + r) * (3 * D_) + h * 192 + 128 + c];
        }
        __syncthreads();

#pragma unroll 8
        for (int kk = 0; kk < 64; kk++) {
            float a[4], bb[4];
#pragma unroll
            for (int i = 0; i < 4; i++) a[i]  = Ps[ty * 4 + i][kk];
#pragma unroll
            for (int j = 0; j < 4; j++) bb[j] = Vs[kk][tx * 4 + j];
#pragma unroll
            for (int i = 0; i < 4; i++)
#pragma unroll
                for (int j = 0; j < 4; j++)
                    acc[i][j] = fmaf(a[i], bb[j], acc[i][j]);
        }
        __syncthreads();
    }

#pragma unroll
    for (int i = 0; i < 4; i++) {
        int q = q0 + ty * 4 + i;
#pragma unroll
        for (int j = 0; j < 4; j++) {
            int d = tx * 4 + j;
            g_attn[(size_t)(b * S_ + q) * D_ + h * 64 + d] = acc[i][j];
        }
    }
}

// ---------------------------------------------------------------------------
// Host launcher
// ---------------------------------------------------------------------------
extern "C" void kernel_launch(void* const* d_in, const int* in_sizes, int n_in,
                              void* d_out, int out_size)
{
    const int*   idx     = (const int*)  d_in[0];
    const float* tok_emb = (const float*)d_in[1];
    const float* pos_emb = (const float*)d_in[2];
    const float* qkv_w   = (const float*)d_in[3];
    const float* proj_w  = (const float*)d_in[4];
    const float* proj_b  = (const float*)d_in[5];
    const float* ln1_s   = (const float*)d_in[6];
    const float* ln1_b   = (const float*)d_in[7];
    const float* fc1_w   = (const float*)d_in[8];
    const float* fc1_b   = (const float*)d_in[9];
    const float* fc2_w   = (const float*)d_in[10];
    const float* fc2_b   = (const float*)d_in[11];
    const float* ln2_s   = (const float*)d_in[12];
    const float* ln2_b   = (const float*)d_in[13];
    const float* lnf_s   = (const float*)d_in[14];
    const float* lnf_b   = (const float*)d_in[15];
    const float* head_w  = (const float*)d_in[16];
    const float* head_b  = (const float*)d_in[17];
    float* out = (float*)d_out;

    float *x, *h, *qkv, *attn, *ffh;
    cudaGetSymbolAddress((void**)&x,    g_x);
    cudaGetSymbolAddress((void**)&h,    g_h);
    cudaGetSymbolAddress((void**)&qkv,  g_qkv);
    cudaGetSymbolAddress((void**)&attn, g_attn);
    cudaGetSymbolAddress((void**)&ffh,  g_ffh);

    embed_kernel<<<NTOK, 256>>>(idx, tok_emb, pos_emb);

    for (int l = 0; l < L_; l++) {
        // ln1
        ln_kernel<<<NTOK, 256>>>(x, h, ln1_s + l * D_, ln1_b + l * D_);
        // qkv = h @ qkv_w^T
        gemm_kernel<<<dim3(3 * D_ / 128, NTOK / 128), 256>>>(
            h, qkv_w + (size_t)l * 3 * D_ * D_, nullptr, nullptr, qkv,
            NTOK, 3 * D_, D_, 0);
        // attention
        scores_kernel<<<dim3(S_ / 64, S_ / 64, B_ * H_), 256>>>();
        softmax_kernel<<<B_ * H_ * S_, 256>>>();
        attnout_kernel<<<dim3(S_ / 64, B_ * H_), 256>>>();
        // x = x + attn @ proj_w^T + proj_b
        gemm_kernel<<<dim3(D_ / 128, NTOK / 128), 256>>>(
            attn, proj_w + (size_t)l * D_ * D_, proj_b + l * D_, x, x,
            NTOK, D_, D_, 0);
        // ln2
        ln_kernel<<<NTOK, 256>>>(x, h, ln2_s + l * D_, ln2_b + l * D_);
        // ffh = relu(h @ fc1_w^T + fc1_b)
        gemm_kernel<<<dim3(FF_ / 128, NTOK / 128), 256>>>(
            h, fc1_w + (size_t)l * FF_ * D_, fc1_b + l * FF_, nullptr, ffh,
            NTOK, FF_, D_, 1);
        // x = x + ffh @ fc2_w^T + fc2_b
        gemm_kernel<<<dim3(D_ / 128, NTOK / 128), 256>>>(
            ffh, fc2_w + (size_t)l * D_ * FF_, fc2_b + l * D_, x, x,
            NTOK, D_, FF_, 0);
    }

    // final LN + head
    ln_kernel<<<NTOK, 256>>>(x, h, lnf_s, lnf_b);
    gemm_kernel<<<dim3((V_ + 127) / 128, NTOK / 128), 256>>>(
        h, head_w, head_b, nullptr, out, NTOK, V_, D_, 0);
}

// round 2
// speedup vs baseline: 1.6661x; 1.6661x over previous
#include <cuda_runtime.h>
#include <cuda_bf16.h>
#include <math.h>
#include <stdint.h>

// Problem constants
#define B_  2
#define S_  1024
#define D_  1024
#define H_  16
#define HD_ 64
#define L_  8
#define FF_ 4096
#define V_  50257
#define EPS_ 1e-5f
#define NTOK (B_ * S_)          // 2048 rows

// ---------------------------------------------------------------------------
// Scratch buffers (static device globals — allocation-free)
// ---------------------------------------------------------------------------
__device__ float g_x[NTOK * D_];                         // residual stream   8 MB
__device__ float g_h[NTOK * D_];                         // ln output         8 MB
__device__ float g_qkv[NTOK * 3 * D_];                   // qkv proj         24 MB
__device__ float g_scores[(size_t)B_ * H_ * S_ * S_];    // attn scores     128 MB
__device__ float g_attn[NTOK * D_];                      // attn output      8 MB
__device__ float g_ffh[NTOK * FF_];                      // mlp hidden      32 MB

// ---------------------------------------------------------------------------
// PTX helpers
// ---------------------------------------------------------------------------
__device__ __forceinline__ uint32_t smem_u32(const void* p) {
    return (uint32_t)__cvta_generic_to_shared(p);
}
__device__ __forceinline__ void ldsm4(uint32_t& r0, uint32_t& r1,
                                      uint32_t& r2, uint32_t& r3, uint32_t addr) {
    asm volatile("ldmatrix.sync.aligned.m8n8.x4.shared.b16 {%0,%1,%2,%3},[%4];"
                 : "=r"(r0), "=r"(r1), "=r"(r2), "=r"(r3) : "r"(addr));
}
__device__ __forceinline__ void mma16816(float* c, const uint32_t* a,
                                         uint32_t b0, uint32_t b1) {
    asm volatile(
        "mma.sync.aligned.m16n8k16.row.col.f32.bf16.bf16.f32 "
        "{%0,%1,%2,%3},{%4,%5,%6,%7},{%8,%9},{%0,%1,%2,%3};"
        : "+f"(c[0]), "+f"(c[1]), "+f"(c[2]), "+f"(c[3])
        : "r"(a[0]), "r"(a[1]), "r"(a[2]), "r"(a[3]), "r"(b0), "r"(b1));
}

// ---------------------------------------------------------------------------
// Embedding
// ---------------------------------------------------------------------------
__global__ void embed_kernel(const int* __restrict__ idx,
                             const float* __restrict__ tok,
                             const float* __restrict__ pos)
{
    int row = blockIdx.x;
    int s = row % S_;
    int t = idx[row];
    const float* te = tok + (size_t)t * D_;
    const float* pe = pos + (size_t)s * D_;
    float* o = g_x + (size_t)row * D_;
    for (int c = threadIdx.x; c < D_; c += blockDim.x)
        o[c] = te[c] + pe[c];
}

// ---------------------------------------------------------------------------
// LayerNorm
// ---------------------------------------------------------------------------
__global__ void __launch_bounds__(256) ln_kernel(const float* __restrict__ in,
                                                 float* __restrict__ out,
                                                 const float* __restrict__ sc,
                                                 const float* __restrict__ bi)
{
    int row = blockIdx.x;
    const float* x = in + (size_t)row * D_;
    float* y = out + (size_t)row * D_;
    __shared__ float red[256];
    int tid = threadIdx.x;

    float s = 0.f;
    for (int c = tid; c < D_; c += 256) s += x[c];
    red[tid] = s; __syncthreads();
    for (int o = 128; o > 0; o >>= 1) {
        if (tid < o) red[tid] += red[tid + o];
        __syncthreads();
    }
    float mu = red[0] * (1.f / D_);
    __syncthreads();

    float v = 0.f;
    for (int c = tid; c < D_; c += 256) { float d = x[c] - mu; v += d * d; }
    red[tid] = v; __syncthreads();
    for (int o = 128; o > 0; o >>= 1) {
        if (tid < o) red[tid] += red[tid + o];
        __syncthreads();
    }
    float rstd = rsqrtf(red[0] * (1.f / D_) + EPS_);

    for (int c = tid; c < D_; c += 256)
        y[c] = (x[c] - mu) * rstd * sc[c] + bi[c];
}

// ---------------------------------------------------------------------------
// bf16x3 tensor-core GEMM:
//   C[M,N] = A[M,K] * B[N,K]^T (+bias[n]) (ReLU) (+res[M,N])
// fp32 inputs split on the fly into bf16 hi+lo; 3 MMAs (hh, hl, lh) per tile.
// Block tile 128x128, BK=32, 512 threads (16 warps, 32x32 each).
// M must be a multiple of 128 (always true: NTOK=2048). N may be ragged.
// K must be a multiple of 32 (1024 / 4096).
// ---------------------------------------------------------------------------
#define PADK 40   // 32 + 8 bf16 pad (80B row stride -> conflict-free ldmatrix)

__global__ void __launch_bounds__(512) gemm_bf16x3_kernel(
    const float* __restrict__ A, const float* __restrict__ Bw,
    const float* __restrict__ bias, const float* __restrict__ res,
    float* __restrict__ C, int M, int N, int K, int relu)
{
    __shared__ __nv_bfloat16 Ah[128][PADK];
    __shared__ __nv_bfloat16 Al[128][PADK];
    __shared__ __nv_bfloat16 Bh[128][PADK];
    __shared__ __nv_bfloat16 Bl[128][PADK];

    int tid  = threadIdx.x;
    int lane = tid & 31;
    int wid  = tid >> 5;            // 0..15
    int wm = (wid & 3) * 32;        // warp m offset within tile
    int wn = (wid >> 2) * 32;       // warp n offset within tile
    int m0 = blockIdx.y * 128;
    int n0 = blockIdx.x * 128;

    float acc[2][4][4];             // [mt][nt][frag]
#pragma unroll
    for (int i = 0; i < 2; i++)
#pragma unroll
        for (int j = 0; j < 4; j++)
#pragma unroll
            for (int k = 0; k < 4; k++) acc[i][j][k] = 0.f;

    int g = lane >> 3, r = lane & 7;

    for (int k0 = 0; k0 < K; k0 += 32) {
        // ---- stage 128x32 of A and B, split into hi/lo bf16 ----
#pragma unroll
        for (int i = 0; i < 2; i++) {
            int idx = tid + i * 512;          // 0..1023
            int row = idx >> 3;
            int c4  = (idx & 7) * 4;
            float4 av = *(const float4*)&A[(size_t)(m0 + row) * K + k0 + c4];
            int bRow = n0 + row;
            float4 bv = (bRow < N)
                ? *(const float4*)&Bw[(size_t)bRow * K + k0 + c4]
                : make_float4(0.f, 0.f, 0.f, 0.f);
            float va[4] = {av.x, av.y, av.z, av.w};
            float vb[4] = {bv.x, bv.y, bv.z, bv.w};
#pragma unroll
            for (int j = 0; j < 4; j++) {
                __nv_bfloat16 h = __float2bfloat16(va[j]);
                Ah[row][c4 + j] = h;
                Al[row][c4 + j] = __float2bfloat16(va[j] - __bfloat162float(h));
                __nv_bfloat16 hb = __float2bfloat16(vb[j]);
                Bh[row][c4 + j] = hb;
                Bl[row][c4 + j] = __float2bfloat16(vb[j] - __bfloat162float(hb));
            }
        }
        __syncthreads();

        // ---- two k-steps of 16 ----
#pragma unroll
        for (int ks = 0; ks < 2; ks++) {
            // A fragments: mt in {0,1}, x4 covers 16 rows x 16 cols
            uint32_t ah[2][4], al[2][4];
#pragma unroll
            for (int mt = 0; mt < 2; mt++) {
                int srow = wm + mt * 16 + (g & 1) * 8 + r;
                int scol = ks * 16 + (g >> 1) * 8;
                ldsm4(ah[mt][0], ah[mt][1], ah[mt][2], ah[mt][3],
                      smem_u32(&Ah[srow][scol]));
                ldsm4(al[mt][0], al[mt][1], al[mt][2], al[mt][3],
                      smem_u32(&Al[srow][scol]));
            }
            // B fragments: 2 x4 loads cover 4 n-tiles of 8
            uint32_t bh[2][4], bl[2][4];
#pragma unroll
            for (int p = 0; p < 2; p++) {
                int srow = wn + p * 16 + (g >> 1) * 8 + r;
                int scol = ks * 16 + (g & 1) * 8;
                ldsm4(bh[p][0], bh[p][1], bh[p][2], bh[p][3],
                      smem_u32(&Bh[srow][scol]));
                ldsm4(bl[p][0], bl[p][1], bl[p][2], bl[p][3],
                      smem_u32(&Bl[srow][scol]));
            }
#pragma unroll
            for (int mt = 0; mt < 2; mt++)
#pragma unroll
                for (int nt = 0; nt < 4; nt++) {
                    int p = nt >> 1, o = (nt & 1) * 2;
                    mma16816(acc[mt][nt], ah[mt], bh[p][o], bh[p][o + 1]); // hi*hi
                    mma16816(acc[mt][nt], ah[mt], bl[p][o], bl[p][o + 1]); // hi*lo
                    mma16816(acc[mt][nt], al[mt], bh[p][o], bh[p][o + 1]); // lo*hi
                }
        }
        __syncthreads();
    }

    // ---- epilogue ----
#pragma unroll
    for (int mt = 0; mt < 2; mt++) {
#pragma unroll
        for (int nt = 0; nt < 4; nt++) {
            int mr = m0 + wm + mt * 16 + (lane >> 2);
            int nc = n0 + wn + nt * 8 + (lane & 3) * 2;
#pragma unroll
            for (int half = 0; half < 2; half++) {
                int m = mr + half * 8;
#pragma unroll
                for (int j = 0; j < 2; j++) {
                    int n = nc + j;
                    if (n >= N) continue;
                    float v = acc[mt][nt][half * 2 + j];
                    if (bias) v += bias[n];
                    if (relu) v = fmaxf(v, 0.f);
                    if (res)  v += res[(size_t)m * N + n];
                    C[(size_t)m * N + n] = v;
                }
            }
        }
    }
}

// ---------------------------------------------------------------------------
// Attention scores (fp32, causal tile skip)
// ---------------------------------------------------------------------------
__global__ void __launch_bounds__(256) scores_kernel()
{
    int q0 = blockIdx.x * 64;
    int k0 = blockIdx.y * 64;
    if (k0 > q0 + 63) return;
    int bh = blockIdx.z;
    int b = bh >> 4, h = bh & 15;

    __shared__ float Qs[64][65];
    __shared__ float Ks[64][65];
    int tid = threadIdx.x;

    for (int i = tid; i < 64 * 64; i += 256) {
        int r = i >> 6, c = i & 63;
        Qs[r][c] = g_qkv[(size_t)(b * S_ + q0 + r) * (3 * D_) + h * 192 + c];
        Ks[r][c] = g_qkv[(size_t)(b * S_ + k0 + r) * (3 * D_) + h * 192 + 64 + c];
    }
    __syncthreads();

    int ty = tid >> 4, tx = tid & 15;
    float acc[4][4];
#pragma unroll
    for (int i = 0; i < 4; i++)
#pragma unroll
        for (int j = 0; j < 4; j++) acc[i][j] = 0.f;

#pragma unroll 8
    for (int d = 0; d < 64; d++) {
        float a[4], bb[4];
#pragma unroll
        for (int i = 0; i < 4; i++) a[i]  = Qs[ty * 4 + i][d];
#pragma unroll
        for (int j = 0; j < 4; j++) bb[j] = Ks[tx * 4 + j][d];
#pragma unroll
        for (int i = 0; i < 4; i++)
#pragma unroll
            for (int j = 0; j < 4; j++)
                acc[i][j] = fmaf(a[i], bb[j], acc[i][j]);
    }

    const float scale = 0.125f;
#pragma unroll
    for (int i = 0; i < 4; i++) {
        int q = q0 + ty * 4 + i;
#pragma unroll
        for (int j = 0; j < 4; j++) {
            int k = k0 + tx * 4 + j;
            g_scores[((size_t)bh * S_ + q) * S_ + k] = acc[i][j] * scale;
        }
    }
}

// ---------------------------------------------------------------------------
// Causal softmax (zero-fills the masked tail)
// ---------------------------------------------------------------------------
__global__ void __launch_bounds__(256) softmax_kernel()
{
    int row = blockIdx.x;
    int q = row & (S_ - 1);
    float* p = g_scores + (size_t)row * S_;
    int valid = q + 1;
    int tid = threadIdx.x;
    __shared__ float red[256];

    float m = -1e30f;
    for (int c = tid; c < valid; c += 256) m = fmaxf(m, p[c]);
    red[tid] = m; __syncthreads();
    for (int o = 128; o > 0; o >>= 1) {
        if (tid < o) red[tid] = fmaxf(red[tid], red[tid + o]);
        __syncthreads();
    }
    m = red[0]; __syncthreads();

    float s = 0.f;
    for (int c = tid; c < valid; c += 256) {
        float e = __expf(p[c] - m);
        p[c] = e;
        s += e;
    }
    red[tid] = s; __syncthreads();
    for (int o = 128; o > 0; o >>= 1) {
        if (tid < o) red[tid] += red[tid + o];
        __syncthreads();
    }
    float inv = 1.f / red[0];

    for (int c = tid; c < valid; c += 256) p[c] *= inv;
    for (int c = valid + tid; c < S_; c += 256) p[c] = 0.f;
}

// ---------------------------------------------------------------------------
// P @ V (fp32, causal chunk skip)
// ---------------------------------------------------------------------------
__global__ void __launch_bounds__(256) attnout_kernel()
{
    int q0 = blockIdx.x * 64;
    int bh = blockIdx.y;
    int b = bh >> 4, h = bh & 15;

    __shared__ float Ps[64][65];
    __shared__ float Vs[64][65];
    int tid = threadIdx.x;
    int ty = tid >> 4, tx = tid & 15;

    float acc[4][4];
#pragma unroll
    for (int i = 0; i < 4; i++)
#pragma unroll
        for (int j = 0; j < 4; j++) acc[i][j] = 0.f;

    int nChunks = (q0 >> 6) + 1;
    for (int kc = 0; kc < nChunks; kc++) {
        int k0 = kc * 64;
        for (int i = tid; i < 64 * 64; i += 256) {
            int r = i >> 6, c = i & 63;
            Ps[r][c] = g_scores[((size_t)bh * S_ + q0 + r) * S_ + k0 + c];
            Vs[r][c] = g_qkv[(size_t)(b * S_ + k0 + r) * (3 * D_) + h * 192 + 128 + c];
        }
        __syncthreads();

#pragma unroll 8
        for (int kk = 0; kk < 64; kk++) {
            float a[4], bb[4];
#pragma unroll
            for (int i = 0; i < 4; i++) a[i]  = Ps[ty * 4 + i][kk];
#pragma unroll
            for (int j = 0; j < 4; j++) bb[j] = Vs[kk][tx * 4 + j];
#pragma unroll
            for (int i = 0; i < 4; i++)
#pragma unroll
                for (int j = 0; j < 4; j++)
                    acc[i][j] = fmaf(a[i], bb[j], acc[i][j]);
        }
        __syncthreads();
    }

#pragma unroll
    for (int i = 0; i < 4; i++) {
        int q = q0 + ty * 4 + i;
#pragma unroll
        for (int j = 0; j < 4; j++) {
            int d = tx * 4 + j;
            g_attn[(size_t)(b * S_ + q) * D_ + h * 64 + d] = acc[i][j];
        }
    }
}

// ---------------------------------------------------------------------------
// Host launcher
// ---------------------------------------------------------------------------
extern "C" void kernel_launch(void* const* d_in, const int* in_sizes, int n_in,
                              void* d_out, int out_size)
{
    const int*   idx     = (const int*)  d_in[0];
    const float* tok_emb = (const float*)d_in[1];
    const float* pos_emb = (const float*)d_in[2];
    const float* qkv_w   = (const float*)d_in[3];
    const float* proj_w  = (const float*)d_in[4];
    const float* proj_b  = (const float*)d_in[5];
    const float* ln1_s   = (const float*)d_in[6];
    const float* ln1_b   = (const float*)d_in[7];
    const float* fc1_w   = (const float*)d_in[8];
    const float* fc1_b   = (const float*)d_in[9];
    const float* fc2_w   = (const float*)d_in[10];
    const float* fc2_b   = (const float*)d_in[11];
    const float* ln2_s   = (const float*)d_in[12];
    const float* ln2_b   = (const float*)d_in[13];
    const float* lnf_s   = (const float*)d_in[14];
    const float* lnf_b   = (const float*)d_in[15];
    const float* head_w  = (const float*)d_in[16];
    const float* head_b  = (const float*)d_in[17];
    float* out = (float*)d_out;

    float *x, *h, *qkv, *attn, *ffh;
    cudaGetSymbolAddress((void**)&x,    g_x);
    cudaGetSymbolAddress((void**)&h,    g_h);
    cudaGetSymbolAddress((void**)&qkv,  g_qkv);
    cudaGetSymbolAddress((void**)&attn, g_attn);
    cudaGetSymbolAddress((void**)&ffh,  g_ffh);

    embed_kernel<<<NTOK, 256>>>(idx, tok_emb, pos_emb);

    for (int l = 0; l < L_; l++) {
        ln_kernel<<<NTOK, 256>>>(x, h, ln1_s + l * D_, ln1_b + l * D_);
        gemm_bf16x3_kernel<<<dim3(3 * D_ / 128, NTOK / 128), 512>>>(
            h, qkv_w + (size_t)l * 3 * D_ * D_, nullptr, nullptr, qkv,
            NTOK, 3 * D_, D_, 0);
        scores_kernel<<<dim3(S_ / 64, S_ / 64, B_ * H_), 256>>>();
        softmax_kernel<<<B_ * H_ * S_, 256>>>();
        attnout_kernel<<<dim3(S_ / 64, B_ * H_), 256>>>();
        gemm_bf16x3_kernel<<<dim3(D_ / 128, NTOK / 128), 512>>>(
            attn, proj_w + (size_t)l * D_ * D_, proj_b + l * D_, x, x,
            NTOK, D_, D_, 0);
        ln_kernel<<<NTOK, 256>>>(x, h, ln2_s + l * D_, ln2_b + l * D_);
        gemm_bf16x3_kernel<<<dim3(FF_ / 128, NTOK / 128), 512>>>(
            h, fc1_w + (size_t)l * FF_ * D_, fc1_b + l * FF_, nullptr, ffh,
            NTOK, FF_, D_, 1);
        gemm_bf16x3_kernel<<<dim3(D_ / 128, NTOK / 128), 512>>>(
            ffh, fc2_w + (size_t)l * D_ * FF_, fc2_b + l * D_, x, x,
            NTOK, D_, FF_, 0);
    }

    ln_kernel<<<NTOK, 256>>>(x, h, lnf_s, lnf_b);
    gemm_bf16x3_kernel<<<dim3((V_ + 127) / 128, NTOK / 128), 512>>>(
        h, head_w, head_b, nullptr, out, NTOK, V_, D_, 0);
}

// round 4
// speedup vs baseline: 2.2837x; 1.3707x over previous
#include <cuda_runtime.h>
#include <cuda_bf16.h>
#include <math.h>
#include <stdint.h>

// Problem constants
#define B_  2
#define S_  1024
#define D_  1024
#define H_  16
#define HD_ 64
#define L_  8
#define FF_ 4096
#define V_  50257
#define EPS_ 1e-5f
#define NTOK (B_ * S_)          // 2048 rows

// ---------------------------------------------------------------------------
// Scratch buffers (static device globals — allocation-free)
// ---------------------------------------------------------------------------
__device__ float g_x[NTOK * D_];                       // residual stream fp32
__device__ float g_qkv[NTOK * 3 * D_];                 // qkv output fp32
__device__ float g_scores[(size_t)B_ * H_ * S_ * S_];  // attn scores fp32

// activations as bf16 hi/lo (GEMM A operands)
__device__ __nv_bfloat16 g_h_hi[NTOK * D_],   g_h_lo[NTOK * D_];
__device__ __nv_bfloat16 g_at_hi[NTOK * D_],  g_at_lo[NTOK * D_];
__device__ __nv_bfloat16 g_ff_hi[NTOK * FF_], g_ff_lo[NTOK * FF_];

// weights as bf16 hi/lo (GEMM B operands), split once per call
#define NQKV (L_ * 3 * D_ * D_)
#define NPROJ (L_ * D_ * D_)
#define NFC1 (L_ * FF_ * D_)
#define NFC2 (L_ * D_ * FF_)
#define NHEAD (V_ * D_)
__device__ __nv_bfloat16 w_qkv_hi[NQKV],  w_qkv_lo[NQKV];
__device__ __nv_bfloat16 w_proj_hi[NPROJ], w_proj_lo[NPROJ];
__device__ __nv_bfloat16 w_fc1_hi[NFC1],  w_fc1_lo[NFC1];
__device__ __nv_bfloat16 w_fc2_hi[NFC2],  w_fc2_lo[NFC2];
__device__ __nv_bfloat16 w_head_hi[NHEAD], w_head_lo[NHEAD];

// ---------------------------------------------------------------------------
// PTX helpers
// ---------------------------------------------------------------------------
__device__ __forceinline__ uint32_t smem_u32(const void* p) {
    return (uint32_t)__cvta_generic_to_shared(p);
}
__device__ __forceinline__ void ldsm4(uint32_t& r0, uint32_t& r1,
                                      uint32_t& r2, uint32_t& r3, uint32_t addr) {
    asm volatile("ldmatrix.sync.aligned.m8n8.x4.shared.b16 {%0,%1,%2,%3},[%4];"
                 : "=r"(r0), "=r"(r1), "=r"(r2), "=r"(r3) : "r"(addr));
}
__device__ __forceinline__ void mma16816(float* c, const uint32_t* a,
                                         uint32_t b0, uint32_t b1) {
    asm volatile(
        "mma.sync.aligned.m16n8k16.row.col.f32.bf16.bf16.f32 "
        "{%0,%1,%2,%3},{%4,%5,%6,%7},{%8,%9},{%0,%1,%2,%3};"
        : "+f"(c[0]), "+f"(c[1]), "+f"(c[2]), "+f"(c[3])
        : "r"(a[0]), "r"(a[1]), "r"(a[2]), "r"(a[3]), "r"(b0), "r"(b1));
}
__device__ __forceinline__ void cp_async16(uint32_t dst, const void* src, bool valid) {
    int sz = valid ? 16 : 0;
    asm volatile("cp.async.cg.shared.global [%0], [%1], 16, %2;"
                 :: "r"(dst), "l"(src), "r"(sz) : "memory");
}
#define CP_COMMIT() asm volatile("cp.async.commit_group;" ::: "memory")
#define CP_WAIT1()  asm volatile("cp.async.wait_group 1;" ::: "memory")

// ---------------------------------------------------------------------------
// Weight split kernel: fp32 -> bf16 (hi, lo), grid-stride over float4
// ---------------------------------------------------------------------------
__global__ void __launch_bounds__(256) split_kernel(
    const float* __restrict__ src, __nv_bfloat16* __restrict__ hi,
    __nv_bfloat16* __restrict__ lo, int n4)
{
    int i = blockIdx.x * blockDim.x + threadIdx.x;
    int stride = gridDim.x * blockDim.x;
    for (; i < n4; i += stride) {
        float4 v = ((const float4*)src)[i];
        float f[4] = {v.x, v.y, v.z, v.w};
        __nv_bfloat16 h[4], l[4];
#pragma unroll
        for (int j = 0; j < 4; j++) {
            h[j] = __float2bfloat16(f[j]);
            l[j] = __float2bfloat16(f[j] - __bfloat162float(h[j]));
        }
        ((uint2*)hi)[i] = *(uint2*)h;
        ((uint2*)lo)[i] = *(uint2*)l;
    }
}

// ---------------------------------------------------------------------------
// bf16x3 HMMA GEMM with 3-stage cp.async pipeline.
//   C[M,N] = A[M,K] * B[N,K]^T (+bias)(ReLU)(+res)
// A and B pre-split into bf16 hi/lo. 128x128 tile, BK=32, 512 threads.
// Output: fp32 (Cf != nullptr) OR bf16 hi/lo split (Chi/Clo).
// M % 128 == 0, K % 32 == 0. N may be ragged.
// ---------------------------------------------------------------------------
#define BK 32
#define PADK 40                    // bf16 per smem row (80 B, 16B-aligned)
#define ARR_B (128 * PADK * 2)     // 10240 bytes per array
#define STG_B (4 * ARR_B)          // 40960 bytes per stage
#define STAGES 3
#define GEMM_SMEM (STAGES * STG_B) // 122880

__global__ void __launch_bounds__(512, 1) gemm_tc(
    const __nv_bfloat16* __restrict__ Ah, const __nv_bfloat16* __restrict__ Al,
    const __nv_bfloat16* __restrict__ Bh, const __nv_bfloat16* __restrict__ Bl,
    const float* __restrict__ bias, const float* __restrict__ res,
    float* __restrict__ Cf, __nv_bfloat16* __restrict__ Chi,
    __nv_bfloat16* __restrict__ Clo, int M, int N, int K, int relu)
{
    extern __shared__ char smem[];
    int tid  = threadIdx.x;
    int lane = tid & 31;
    int wid  = tid >> 5;
    int wm = (wid & 3) * 32;
    int wn = (wid >> 2) * 32;
    int m0 = blockIdx.y * 128;
    int n0 = blockIdx.x * 128;
    int g = lane >> 3, r = lane & 7;

    // per-thread load coords: 512 threads cover 128 rows x 2 segs x ... 
    int ldRow = tid >> 2;          // 0..127
    int ldSeg = tid & 3;           // 16B segment (8 bf16)
    int bRow = n0 + ldRow;
    bool bValid = bRow < N;
    size_t aOff = (size_t)(m0 + ldRow) * K + ldSeg * 8;
    size_t bOff = (size_t)(bValid ? bRow : 0) * K + ldSeg * 8;
    uint32_t dstRow = smem_u32(smem) + ldRow * (PADK * 2) + ldSeg * 16;

    int nk = K / BK;

    float acc[2][4][4];
#pragma unroll
    for (int i = 0; i < 2; i++)
#pragma unroll
        for (int j = 0; j < 4; j++)
#pragma unroll
            for (int k = 0; k < 4; k++) acc[i][j][k] = 0.f;

    // prologue: stages 0..STAGES-2
#pragma unroll
    for (int s = 0; s < STAGES - 1; s++) {
        int k0 = s * BK;
        uint32_t d = dstRow + s * STG_B;
        cp_async16(d,             Ah + aOff + k0, true);
        cp_async16(d + ARR_B,     Al + aOff + k0, true);
        cp_async16(d + 2 * ARR_B, Bh + bOff + k0, bValid);
        cp_async16(d + 3 * ARR_B, Bl + bOff + k0, bValid);
        CP_COMMIT();
    }

    for (int kc = 0; kc < nk; kc++) {
        CP_WAIT1();
        __syncthreads();

        // issue load for stage kc+STAGES-1
        int kl = kc + STAGES - 1;
        if (kl < nk) {
            int k0 = kl * BK;
            uint32_t d = dstRow + (kl % STAGES) * STG_B;
            cp_async16(d,             Ah + aOff + k0, true);
            cp_async16(d + ARR_B,     Al + aOff + k0, true);
            cp_async16(d + 2 * ARR_B, Bh + bOff + k0, bValid);
            cp_async16(d + 3 * ARR_B, Bl + bOff + k0, bValid);
        }
        CP_COMMIT();

        // compute stage kc
        char* st = smem + (kc % STAGES) * STG_B;
        const __nv_bfloat16 (*SAh)[PADK] = (const __nv_bfloat16(*)[PADK])(st);
        const __nv_bfloat16 (*SAl)[PADK] = (const __nv_bfloat16(*)[PADK])(st + ARR_B);
        const __nv_bfloat16 (*SBh)[PADK] = (const __nv_bfloat16(*)[PADK])(st + 2 * ARR_B);
        const __nv_bfloat16 (*SBl)[PADK] = (const __nv_bfloat16(*)[PADK])(st + 3 * ARR_B);

#pragma unroll
        for (int ks = 0; ks < 2; ks++) {
            uint32_t ah[2][4], al[2][4], bh[2][4], bl[2][4];
#pragma unroll
            for (int mt = 0; mt < 2; mt++) {
                int srow = wm + mt * 16 + (g & 1) * 8 + r;
                int scol = ks * 16 + (g >> 1) * 8;
                ldsm4(ah[mt][0], ah[mt][1], ah[mt][2], ah[mt][3],
                      smem_u32(&SAh[srow][scol]));
                ldsm4(al[mt][0], al[mt][1], al[mt][2], al[mt][3],
                      smem_u32(&SAl[srow][scol]));
            }
#pragma unroll
            for (int p = 0; p < 2; p++) {
                int srow = wn + p * 16 + (g >> 1) * 8 + r;
                int scol = ks * 16 + (g & 1) * 8;
                ldsm4(bh[p][0], bh[p][1], bh[p][2], bh[p][3],
                      smem_u32(&SBh[srow][scol]));
                ldsm4(bl[p][0], bl[p][1], bl[p][2], bl[p][3],
                      smem_u32(&SBl[srow][scol]));
            }
#pragma unroll
            for (int mt = 0; mt < 2; mt++)
#pragma unroll
                for (int nt = 0; nt < 4; nt++) {
                    int p = nt >> 1, o = (nt & 1) * 2;
                    mma16816(acc[mt][nt], ah[mt], bh[p][o], bh[p][o + 1]);
                    mma16816(acc[mt][nt], ah[mt], bl[p][o], bl[p][o + 1]);
                    mma16816(acc[mt][nt], al[mt], bh[p][o], bh[p][o + 1]);
                }
        }
        __syncthreads();
    }

    // ---- epilogue ----
#pragma unroll
    for (int mt = 0; mt < 2; mt++) {
#pragma unroll
        for (int nt = 0; nt < 4; nt++) {
            int mr = m0 + wm + mt * 16 + (lane >> 2);
            int nc = n0 + wn + nt * 8 + (lane & 3) * 2;
#pragma unroll
            for (int half = 0; half < 2; half++) {
                int m = mr + half * 8;
#pragma unroll
                for (int j = 0; j < 2; j++) {
                    int n = nc + j;
                    if (n >= N) continue;
                    float v = acc[mt][nt][half * 2 + j];
                    if (bias) v += bias[n];
                    if (relu) v = fmaxf(v, 0.f);
                    if (Cf) {
                        if (res) v += res[(size_t)m * N + n];
                        Cf[(size_t)m * N + n] = v;
                    } else {
                        __nv_bfloat16 hv = __float2bfloat16(v);
                        Chi[(size_t)m * N + n] = hv;
                        Clo[(size_t)m * N + n] =
                            __float2bfloat16(v - __bfloat162float(hv));
                    }
                }
            }
        }
    }
}

// ---------------------------------------------------------------------------
// Embedding
// ---------------------------------------------------------------------------
__global__ void embed_kernel(const int* __restrict__ idx,
                             const float* __restrict__ tok,
                             const float* __restrict__ pos)
{
    int row = blockIdx.x;
    int s = row % S_;
    int t = idx[row];
    const float* te = tok + (size_t)t * D_;
    const float* pe = pos + (size_t)s * D_;
    float* o = g_x + (size_t)row * D_;
    for (int c = threadIdx.x; c < D_; c += blockDim.x)
        o[c] = te[c] + pe[c];
}

// ---------------------------------------------------------------------------
// LayerNorm (fp32 in -> bf16 hi/lo out)
// ---------------------------------------------------------------------------
__global__ void __launch_bounds__(256) ln_kernel(const float* __restrict__ in,
                                                 __nv_bfloat16* __restrict__ yh,
                                                 __nv_bfloat16* __restrict__ yl,
                                                 const float* __restrict__ sc,
                                                 const float* __restrict__ bi)
{
    int row = blockIdx.x;
    const float* x = in + (size_t)row * D_;
    __shared__ float red[256];
    int tid = threadIdx.x;

    float s = 0.f;
    for (int c = tid; c < D_; c += 256) s += x[c];
    red[tid] = s; __syncthreads();
    for (int o = 128; o > 0; o >>= 1) {
        if (tid < o) red[tid] += red[tid + o];
        __syncthreads();
    }
    float mu = red[0] * (1.f / D_);
    __syncthreads();

    float v = 0.f;
    for (int c = tid; c < D_; c += 256) { float d = x[c] - mu; v += d * d; }
    red[tid] = v; __syncthreads();
    for (int o = 128; o > 0; o >>= 1) {
        if (tid < o) red[tid] += red[tid + o];
        __syncthreads();
    }
    float rstd = rsqrtf(red[0] * (1.f / D_) + EPS_);

    for (int c = tid; c < D_; c += 256) {
        float y = (x[c] - mu) * rstd * sc[c] + bi[c];
        __nv_bfloat16 h = __float2bfloat16(y);
        yh[(size_t)row * D_ + c] = h;
        yl[(size_t)row * D_ + c] = __float2bfloat16(y - __bfloat162float(h));
    }
}

// ---------------------------------------------------------------------------
// Attention scores (fp32, causal tile skip)
// ---------------------------------------------------------------------------
__global__ void __launch_bounds__(256) scores_kernel()
{
    int q0 = blockIdx.x * 64;
    int k0 = blockIdx.y * 64;
    if (k0 > q0 + 63) return;
    int bh = blockIdx.z;
    int b = bh >> 4, h = bh & 15;

    __shared__ float Qs[64][65];
    __shared__ float Ks[64][65];
    int tid = threadIdx.x;

    for (int i = tid; i < 64 * 64; i += 256) {
        int r = i >> 6, c = i & 63;
        Qs[r][c] = g_qkv[(size_t)(b * S_ + q0 + r) * (3 * D_) + h * 192 + c];
        Ks[r][c] = g_qkv[(size_t)(b * S_ + k0 + r) * (3 * D_) + h * 192 + 64 + c];
    }
    __syncthreads();

    int ty = tid >> 4, tx = tid & 15;
    float acc[4][4];
#pragma unroll
    for (int i = 0; i < 4; i++)
#pragma unroll
        for (int j = 0; j < 4; j++) acc[i][j] = 0.f;

#pragma unroll 8
    for (int d = 0; d < 64; d++) {
        float a[4], bb[4];
#pragma unroll
        for (int i = 0; i < 4; i++) a[i]  = Qs[ty * 4 + i][d];
#pragma unroll
        for (int j = 0; j < 4; j++) bb[j] = Ks[tx * 4 + j][d];
#pragma unroll
        for (int i = 0; i < 4; i++)
#pragma unroll
            for (int j = 0; j < 4; j++)
                acc[i][j] = fmaf(a[i], bb[j], acc[i][j]);
    }

    const float scale = 0.125f;
#pragma unroll
    for (int i = 0; i < 4; i++) {
        int q = q0 + ty * 4 + i;
#pragma unroll
        for (int j = 0; j < 4; j++) {
            int k = k0 + tx * 4 + j;
            g_scores[((size_t)bh * S_ + q) * S_ + k] = acc[i][j] * scale;
        }
    }
}

// ---------------------------------------------------------------------------
// Causal softmax
// ---------------------------------------------------------------------------
__global__ void __launch_bounds__(256) softmax_kernel()
{
    int row = blockIdx.x;
    int q = row & (S_ - 1);
    float* p = g_scores + (size_t)row * S_;
    int valid = q + 1;
    int tid = threadIdx.x;
    __shared__ float red[256];

    float m = -1e30f;
    for (int c = tid; c < valid; c += 256) m = fmaxf(m, p[c]);
    red[tid] = m; __syncthreads();
    for (int o = 128; o > 0; o >>= 1) {
        if (tid < o) red[tid] = fmaxf(red[tid], red[tid + o]);
        __syncthreads();
    }
    m = red[0]; __syncthreads();

    float s = 0.f;
    for (int c = tid; c < valid; c += 256) {
        float e = __expf(p[c] - m);
        p[c] = e;
        s += e;
    }
    red[tid] = s; __syncthreads();
    for (int o = 128; o > 0; o >>= 1) {
        if (tid < o) red[tid] += red[tid + o];
        __syncthreads();
    }
    float inv = 1.f / red[0];

    for (int c = tid; c < valid; c += 256) p[c] *= inv;
    for (int c = valid + tid; c < S_; c += 256) p[c] = 0.f;
}

// ---------------------------------------------------------------------------
// P @ V (fp32, causal chunk skip) -> bf16 hi/lo output
// ---------------------------------------------------------------------------
__global__ void __launch_bounds__(256) attnout_kernel()
{
    int q0 = blockIdx.x * 64;
    int bh = blockIdx.y;
    int b = bh >> 4, h = bh & 15;

    __shared__ float Ps[64][65];
    __shared__ float Vs[64][65];
    int tid = threadIdx.x;
    int ty = tid >> 4, tx = tid & 15;

    float acc[4][4];
#pragma unroll
    for (int i = 0; i < 4; i++)
#pragma unroll
        for (int j = 0; j < 4; j++) acc[i][j] = 0.f;

    int nChunks = (q0 >> 6) + 1;
    for (int kc = 0; kc < nChunks; kc++) {
        int k0 = kc * 64;
        for (int i = tid; i < 64 * 64; i += 256) {
            int r = i >> 6, c = i & 63;
            Ps[r][c] = g_scores[((size_t)bh * S_ + q0 + r) * S_ + k0 + c];
            Vs[r][c] = g_qkv[(size_t)(b * S_ + k0 + r) * (3 * D_) + h * 192 + 128 + c];
        }
        __syncthreads();

#pragma unroll 8
        for (int kk = 0; kk < 64; kk++) {
            float a[4], bb[4];
#pragma unroll
            for (int i = 0; i < 4; i++) a[i]  = Ps[ty * 4 + i][kk];
#pragma unroll
            for (int j = 0; j < 4; j++) bb[j] = Vs[kk][tx * 4 + j];
#pragma unroll
            for (int i = 0; i < 4; i++)
#pragma unroll
                for (int j = 0; j < 4; j++)
                    acc[i][j] = fmaf(a[i], bb[j], acc[i][j]);
        }
        __syncthreads();
    }

#pragma unroll
    for (int i = 0; i < 4; i++) {
        int q = q0 + ty * 4 + i;
#pragma unroll
        for (int j = 0; j < 4; j++) {
            int d = tx * 4 + j;
            size_t o = (size_t)(b * S_ + q) * D_ + h * 64 + d;
            float v = acc[i][j];
            __nv_bfloat16 hv = __float2bfloat16(v);
            g_at_hi[o] = hv;
            g_at_lo[o] = __float2bfloat16(v - __bfloat162float(hv));
        }
    }
}

// ---------------------------------------------------------------------------
// Host launcher
// ---------------------------------------------------------------------------
extern "C" void kernel_launch(void* const* d_in, const int* in_sizes, int n_in,
                              void* d_out, int out_size)
{
    const int*   idx     = (const int*)  d_in[0];
    const float* tok_emb = (const float*)d_in[1];
    const float* pos_emb = (const float*)d_in[2];
    const float* qkv_w   = (const float*)d_in[3];
    const float* proj_w  = (const float*)d_in[4];
    const float* proj_b  = (const float*)d_in[5];
    const float* ln1_s   = (const float*)d_in[6];
    const float* ln1_b   = (const float*)d_in[7];
    const float* fc1_w   = (const float*)d_in[8];
    const float* fc1_b   = (const float*)d_in[9];
    const float* fc2_w   = (const float*)d_in[10];
    const float* fc2_b   = (const float*)d_in[11];
    const float* ln2_s   = (const float*)d_in[12];
    const float* ln2_b   = (const float*)d_in[13];
    const float* lnf_s   = (const float*)d_in[14];
    const float* lnf_b   = (const float*)d_in[15];
    const float* head_w  = (const float*)d_in[16];
    const float* head_b  = (const float*)d_in[17];
    float* out = (float*)d_out;

    float *x, *qkvp;
    __nv_bfloat16 *hh, *hl, *ath, *atl, *ffh_h, *ffh_l;
    __nv_bfloat16 *wqh, *wql, *wph, *wpl, *w1h, *w1l, *w2h, *w2l, *wHh, *wHl;
    cudaGetSymbolAddress((void**)&x,     g_x);
    cudaGetSymbolAddress((void**)&qkvp,  g_qkv);
    cudaGetSymbolAddress((void**)&hh,    g_h_hi);
    cudaGetSymbolAddress((void**)&hl,    g_h_lo);
    cudaGetSymbolAddress((void**)&ath,   g_at_hi);
    cudaGetSymbolAddress((void**)&atl,   g_at_lo);
    cudaGetSymbolAddress((void**)&ffh_h, g_ff_hi);
    cudaGetSymbolAddress((void**)&ffh_l, g_ff_lo);
    cudaGetSymbolAddress((void**)&wqh,   w_qkv_hi);
    cudaGetSymbolAddress((void**)&wql,   w_qkv_lo);
    cudaGetSymbolAddress((void**)&wph,   w_proj_hi);
    cudaGetSymbolAddress((void**)&wpl,   w_proj_lo);
    cudaGetSymbolAddress((void**)&w1h,   w_fc1_hi);
    cudaGetSymbolAddress((void**)&w1l,   w_fc1_lo);
    cudaGetSymbolAddress((void**)&w2h,   w_fc2_hi);
    cudaGetSymbolAddress((void**)&w2l,   w_fc2_lo);
    cudaGetSymbolAddress((void**)&wHh,   w_head_hi);
    cudaGetSymbolAddress((void**)&wHl,   w_head_lo);

    cudaFuncSetAttribute(gemm_tc,
                         cudaFuncAttributeMaxDynamicSharedMemorySize, GEMM_SMEM);

    // split all weights into bf16 hi/lo (once per call)
    split_kernel<<<2048, 256>>>(qkv_w,  wqh, wql, NQKV / 4);
    split_kernel<<<1024, 256>>>(proj_w, wph, wpl, NPROJ / 4);
    split_kernel<<<2048, 256>>>(fc1_w,  w1h, w1l, NFC1 / 4);
    split_kernel<<<2048, 256>>>(fc2_w,  w2h, w2l, NFC2 / 4);
    split_kernel<<<2048, 256>>>(head_w, wHh, wHl, NHEAD / 4);

    embed_kernel<<<NTOK, 256>>>(idx, tok_emb, pos_emb);

    for (int l = 0; l < L_; l++) {
        ln_kernel<<<NTOK, 256>>>(x, hh, hl, ln1_s + l * D_, ln1_b + l * D_);
        // qkv = h @ qkv_w^T  (fp32 out)
        gemm_tc<<<dim3(3 * D_ / 128, NTOK / 128), 512, GEMM_SMEM>>>(
            hh, hl, wqh + (size_t)l * 3 * D_ * D_, wql + (size_t)l * 3 * D_ * D_,
            nullptr, nullptr, qkvp, nullptr, nullptr, NTOK, 3 * D_, D_, 0);
        scores_kernel<<<dim3(S_ / 64, S_ / 64, B_ * H_), 256>>>();
        softmax_kernel<<<B_ * H_ * S_, 256>>>();
        attnout_kernel<<<dim3(S_ / 64, B_ * H_), 256>>>();
        // x = x + attn @ proj_w^T + proj_b (fp32 out, residual)
        gemm_tc<<<dim3(D_ / 128, NTOK / 128), 512, GEMM_SMEM>>>(
            ath, atl, wph + (size_t)l * D_ * D_, wpl + (size_t)l * D_ * D_,
            proj_b + l * D_, x, x, nullptr, nullptr, NTOK, D_, D_, 0);
        ln_kernel<<<NTOK, 256>>>(x, hh, hl, ln2_s + l * D_, ln2_b + l * D_);
        // ffh = relu(h @ fc1_w^T + fc1_b)  (bf16 hi/lo out)
        gemm_tc<<<dim3(FF_ / 128, NTOK / 128), 512, GEMM_SMEM>>>(
            hh, hl, w1h + (size_t)l * FF_ * D_, w1l + (size_t)l * FF_ * D_,
            fc1_b + l * FF_, nullptr, nullptr, ffh_h, ffh_l, NTOK, FF_, D_, 1);
        // x = x + ffh @ fc2_w^T + fc2_b
        gemm_tc<<<dim3(D_ / 128, NTOK / 128), 512, GEMM_SMEM>>>(
            ffh_h, ffh_l, w2h + (size_t)l * D_ * FF_, w2l + (size_t)l * D_ * FF_,
            fc2_b + l * D_, x, x, nullptr, nullptr, NTOK, D_, FF_, 0);
    }

    ln_kernel<<<NTOK, 256>>>(x, hh, hl, lnf_s, lnf_b);
    gemm_tc<<<dim3((V_ + 127) / 128, NTOK / 128), 512, GEMM_SMEM>>>(
        hh, hl, wHh, wHl, head_b, nullptr, out, nullptr, nullptr,
        NTOK, V_, D_, 0);
}

// round 5
// speedup vs baseline: 3.2324x; 1.4154x over previous
#include <cuda_runtime.h>
#include <cuda_bf16.h>
#include <math.h>
#include <stdint.h>

// Problem constants
#define B_  2
#define S_  1024
#define D_  1024
#define H_  16
#define HD_ 64
#define L_  8
#define FF_ 4096
#define V_  50257
#define EPS_ 1e-5f
#define NTOK (B_ * S_)          // 2048 rows

// ---------------------------------------------------------------------------
// Scratch (static device globals — allocation-free)
// ---------------------------------------------------------------------------
__device__ float g_x[NTOK * D_];                       // residual stream fp32
__device__ float g_qkv[NTOK * 3 * D_];                 // qkv output fp32
__device__ float g_scores[(size_t)B_ * H_ * S_ * S_];  // attn scores fp32
__device__ float g_attn[NTOK * D_];                    // attn out fp32
__device__ float g_ffh[NTOK * FF_];                    // mlp hidden fp32

// int8 split activations (A operands) + per-row scales
__device__ int8_t g_h1[NTOK * D_],  g_h2[NTOK * D_];   __device__ float g_sh[NTOK];
__device__ int8_t g_at1[NTOK * D_], g_at2[NTOK * D_];  __device__ float g_sat[NTOK];
__device__ int8_t g_ff1[NTOK * FF_], g_ff2[NTOK * FF_]; __device__ float g_sff[NTOK];

// int8 split weights (B operands) + per-row scales, quantized once per call
#define NQKV  (L_ * 3 * D_ * D_)
#define NPROJ (L_ * D_ * D_)
#define NFC1  (L_ * FF_ * D_)
#define NFC2  (L_ * D_ * FF_)
#define NHEAD ((size_t)V_ * D_)
__device__ int8_t w_qkv1[NQKV],  w_qkv2[NQKV];   __device__ float s_qkv[L_ * 3 * D_];
__device__ int8_t w_proj1[NPROJ], w_proj2[NPROJ]; __device__ float s_proj[L_ * D_];
__device__ int8_t w_fc11[NFC1],  w_fc12[NFC1];   __device__ float s_fc1[L_ * FF_];
__device__ int8_t w_fc21[NFC2],  w_fc22[NFC2];   __device__ float s_fc2[L_ * D_];
__device__ int8_t w_hd1[NHEAD],  w_hd2[NHEAD];   __device__ float s_hd[V_];

// ---------------------------------------------------------------------------
// PTX helpers
// ---------------------------------------------------------------------------
__device__ __forceinline__ uint32_t smem_u32(const void* p) {
    return (uint32_t)__cvta_generic_to_shared(p);
}
__device__ __forceinline__ void ldsm4(uint32_t& r0, uint32_t& r1,
                                      uint32_t& r2, uint32_t& r3, uint32_t addr) {
    asm volatile("ldmatrix.sync.aligned.m8n8.x4.shared.b16 {%0,%1,%2,%3},[%4];"
                 : "=r"(r0), "=r"(r1), "=r"(r2), "=r"(r3) : "r"(addr));
}
__device__ __forceinline__ void imma16832(int* c, const uint32_t* a,
                                          uint32_t b0, uint32_t b1) {
    asm volatile(
        "mma.sync.aligned.m16n8k32.row.col.s32.s8.s8.s32 "
        "{%0,%1,%2,%3},{%4,%5,%6,%7},{%8,%9},{%0,%1,%2,%3};"
        : "+r"(c[0]), "+r"(c[1]), "+r"(c[2]), "+r"(c[3])
        : "r"(a[0]), "r"(a[1]), "r"(a[2]), "r"(a[3]), "r"(b0), "r"(b1));
}
__device__ __forceinline__ void cp_async16(uint32_t dst, const void* src, bool valid) {
    int sz = valid ? 16 : 0;
    asm volatile("cp.async.cg.shared.global [%0], [%1], 16, %2;"
                 :: "r"(dst), "l"(src), "r"(sz) : "memory");
}
#define CP_COMMIT() asm volatile("cp.async.commit_group;" ::: "memory")
#define CP_WAIT1()  asm volatile("cp.async.wait_group 1;" ::: "memory")

// ---------------------------------------------------------------------------
// Row quantizer: v = s*(q1 + q2/254) + eps, s = rowmax/127. One block per row.
// ---------------------------------------------------------------------------
__global__ void __launch_bounds__(256) quant_kernel(
    const float* __restrict__ src, int8_t* __restrict__ q1,
    int8_t* __restrict__ q2, float* __restrict__ scale, int K)
{
    int row = blockIdx.x;
    const float* v = src + (size_t)row * K;
    __shared__ float red[256];
    int tid = threadIdx.x;

    float m = 0.f;
    for (int c = tid; c < K; c += 256) m = fmaxf(m, fabsf(v[c]));
    red[tid] = m; __syncthreads();
    for (int o = 128; o > 0; o >>= 1) {
        if (tid < o) red[tid] = fmaxf(red[tid], red[tid + o]);
        __syncthreads();
    }
    float rowmax = fmaxf(red[0], 1e-20f);
    if (tid == 0) scale[row] = rowmax * (1.f / 127.f);
    float inv = 127.f / rowmax;

    for (int c = tid; c < K; c += 256) {
        float t = v[c] * inv;
        int a = __float2int_rn(t);
        int b = __float2int_rn((t - (float)a) * 254.f);
        q1[(size_t)row * K + c] = (int8_t)a;
        q2[(size_t)row * K + c] = (int8_t)b;
    }
}

// ---------------------------------------------------------------------------
// LayerNorm fused with row quantization (fp32 in -> int8 q1/q2 + scale)
// ---------------------------------------------------------------------------
__global__ void __launch_bounds__(256) ln_q8_kernel(
    const float* __restrict__ in, int8_t* __restrict__ q1,
    int8_t* __restrict__ q2, float* __restrict__ scale,
    const float* __restrict__ sc, const float* __restrict__ bi)
{
    int row = blockIdx.x;
    const float* x = in + (size_t)row * D_;
    __shared__ float red[256];
    __shared__ float ybuf[D_];
    int tid = threadIdx.x;

    float s = 0.f;
    for (int c = tid; c < D_; c += 256) s += x[c];
    red[tid] = s; __syncthreads();
    for (int o = 128; o > 0; o >>= 1) {
        if (tid < o) red[tid] += red[tid + o];
        __syncthreads();
    }
    float mu = red[0] * (1.f / D_);
    __syncthreads();

    float v = 0.f;
    for (int c = tid; c < D_; c += 256) { float d = x[c] - mu; v += d * d; }
    red[tid] = v; __syncthreads();
    for (int o = 128; o > 0; o >>= 1) {
        if (tid < o) red[tid] += red[tid + o];
        __syncthreads();
    }
    float rstd = rsqrtf(red[0] * (1.f / D_) + EPS_);
    __syncthreads();

    float mx = 0.f;
    for (int c = tid; c < D_; c += 256) {
        float y = (x[c] - mu) * rstd * sc[c] + bi[c];
        ybuf[c] = y;
        mx = fmaxf(mx, fabsf(y));
    }
    red[tid] = mx; __syncthreads();
    for (int o = 128; o > 0; o >>= 1) {
        if (tid < o) red[tid] = fmaxf(red[tid], red[tid + o]);
        __syncthreads();
    }
    float rowmax = fmaxf(red[0], 1e-20f);
    if (tid == 0) scale[row] = rowmax * (1.f / 127.f);
    float inv = 127.f / rowmax;

    for (int c = tid; c < D_; c += 256) {
        float t = ybuf[c] * inv;
        int a = __float2int_rn(t);
        int b = __float2int_rn((t - (float)a) * 254.f);
        q1[(size_t)row * D_ + c] = (int8_t)a;
        q2[(size_t)row * D_ + c] = (int8_t)b;
    }
}

// ---------------------------------------------------------------------------
// int8x3 IMMA GEMM: C[M,N] = A[M,K]*B[N,K]^T (+bias)(ReLU)(+res), fp32 out.
// A,B pre-quantized per-row: v = sA[m](q1+q2/254). 128x128 tile, BK=64 bytes,
// 512 threads, 3-stage cp.async pipeline. M%128==0, K%64==0, N ragged OK.
// ---------------------------------------------------------------------------
#define ROWB 80                     // 64B data + 16B pad (conflict-free)
#define ARR_B (128 * ROWB)          // 10240
#define STG_B (4 * ARR_B)           // 40960
#define STAGES 3
#define GEMM_SMEM (STAGES * STG_B)  // 122880

__global__ void __launch_bounds__(512, 1) gemm_i8(
    const int8_t* __restrict__ A1, const int8_t* __restrict__ A2,
    const float* __restrict__ sA,
    const int8_t* __restrict__ B1, const int8_t* __restrict__ B2,
    const float* __restrict__ sB,
    const float* __restrict__ bias, const float* __restrict__ res,
    float* __restrict__ C, int M, int N, int K, int relu)
{
    extern __shared__ char smem[];
    int tid  = threadIdx.x;
    int lane = tid & 31;
    int wid  = tid >> 5;
    int wm = (wid & 3) * 32;
    int wn = (wid >> 2) * 32;
    int m0 = blockIdx.y * 128;
    int n0 = blockIdx.x * 128;
    int g = lane >> 3, r = lane & 7;

    int ldRow = tid >> 2;           // 0..127
    int ldSeg = tid & 3;            // 16B segment within 64B chunk
    int bRow = n0 + ldRow;
    bool bValid = bRow < N;
    size_t aOff = (size_t)(m0 + ldRow) * K + ldSeg * 16;
    size_t bOff = (size_t)(bValid ? bRow : 0) * K + ldSeg * 16;
    uint32_t dstRow = smem_u32(smem) + ldRow * ROWB + ldSeg * 16;

    int nk = K / 64;

    int acc1[2][4][4], acc2[2][4][4];
#pragma unroll
    for (int i = 0; i < 2; i++)
#pragma unroll
        for (int j = 0; j < 4; j++)
#pragma unroll
            for (int k = 0; k < 4; k++) { acc1[i][j][k] = 0; acc2[i][j][k] = 0; }

#pragma unroll
    for (int s = 0; s < STAGES - 1; s++) {
        int k0 = s * 64;
        uint32_t d = dstRow + s * STG_B;
        cp_async16(d,             A1 + aOff + k0, true);
        cp_async16(d + ARR_B,     A2 + aOff + k0, true);
        cp_async16(d + 2 * ARR_B, B1 + bOff + k0, bValid);
        cp_async16(d + 3 * ARR_B, B2 + bOff + k0, bValid);
        CP_COMMIT();
    }

    for (int kc = 0; kc < nk; kc++) {
        CP_WAIT1();
        __syncthreads();

        int kl = kc + STAGES - 1;
        if (kl < nk) {
            int k0 = kl * 64;
            uint32_t d = dstRow + (kl % STAGES) * STG_B;
            cp_async16(d,             A1 + aOff + k0, true);
            cp_async16(d + ARR_B,     A2 + aOff + k0, true);
            cp_async16(d + 2 * ARR_B, B1 + bOff + k0, bValid);
            cp_async16(d + 3 * ARR_B, B2 + bOff + k0, bValid);
        }
        CP_COMMIT();

        uint32_t st = smem_u32(smem) + (kc % STAGES) * STG_B;

#pragma unroll
        for (int ks = 0; ks < 2; ks++) {
            // A fragments (q1, q2): x4 covers 16 rows x 32 bytes
            uint32_t a1[2][4], a2[2][4];
#pragma unroll
            for (int mt = 0; mt < 2; mt++) {
                uint32_t ad = st + (wm + mt * 16 + (g & 1) * 8 + r) * ROWB
                            + ks * 32 + (g >> 1) * 16;
                ldsm4(a1[mt][0], a1[mt][1], a1[mt][2], a1[mt][3], ad);
                ldsm4(a2[mt][0], a2[mt][1], a2[mt][2], a2[mt][3], ad + ARR_B);
            }
            // B fragments: x4 covers 16 cols x 32 bytes
            // regs: 0: cols 0-7 @k0 | 1: cols 0-7 @k16 | 2: cols 8-15 @k0 | 3: cols 8-15 @k16
            uint32_t b1[2][4], b2[2][4];
#pragma unroll
            for (int p = 0; p < 2; p++) {
                uint32_t bd = st + 2 * ARR_B
                            + (wn + p * 16 + (g >> 1) * 8 + r) * ROWB
                            + ks * 32 + (g & 1) * 16;
                ldsm4(b1[p][0], b1[p][1], b1[p][2], b1[p][3], bd);
                ldsm4(b2[p][0], b2[p][1], b2[p][2], b2[p][3], bd + ARR_B);
            }
#pragma unroll
            for (int mt = 0; mt < 2; mt++)
#pragma unroll
                for (int nt = 0; nt < 4; nt++) {
                    int p = nt >> 1;
                    int o = (nt & 1) * 2;   // 0: regs{0,1}, 1: regs{2,3}
                    imma16832(acc1[mt][nt], a1[mt], b1[p][o], b1[p][o + 1]);
                    imma16832(acc2[mt][nt], a1[mt], b2[p][o], b2[p][o + 1]);
                    imma16832(acc2[mt][nt], a2[mt], b1[p][o], b1[p][o + 1]);
                }
        }
        __syncthreads();
    }

    // ---- epilogue: v = sA[m]*sB[n]*(acc1 + acc2/254) ----
#pragma unroll
    for (int mt = 0; mt < 2; mt++) {
#pragma unroll
        for (int nt = 0; nt < 4; nt++) {
            int mr = m0 + wm + mt * 16 + (lane >> 2);
            int nc = n0 + wn + nt * 8 + (lane & 3) * 2;
#pragma unroll
            for (int half = 0; half < 2; half++) {
                int m = mr + half * 8;
                float sa = sA[m];
#pragma unroll
                for (int j = 0; j < 2; j++) {
                    int n = nc + j;
                    if (n >= N) continue;
                    float v = sa * sB[n] *
                        ((float)acc1[mt][nt][half * 2 + j] +
                         (float)acc2[mt][nt][half * 2 + j] * (1.f / 254.f));
                    if (bias) v += bias[n];
                    if (relu) v = fmaxf(v, 0.f);
                    if (res)  v += res[(size_t)m * N + n];
                    C[(size_t)m * N + n] = v;
                }
            }
        }
    }
}

// ---------------------------------------------------------------------------
// Embedding
// ---------------------------------------------------------------------------
__global__ void embed_kernel(const int* __restrict__ idx,
                             const float* __restrict__ tok,
                             const float* __restrict__ pos)
{
    int row = blockIdx.x;
    int s = row % S_;
    int t = idx[row];
    const float* te = tok + (size_t)t * D_;
    const float* pe = pos + (size_t)s * D_;
    float* o = g_x + (size_t)row * D_;
    for (int c = threadIdx.x; c < D_; c += blockDim.x)
        o[c] = te[c] + pe[c];
}

// ---------------------------------------------------------------------------
// Final LayerNorm variant is just ln_q8 too (head consumes int8).
// ---------------------------------------------------------------------------

// ---------------------------------------------------------------------------
// Attention scores (fp32 FFMA, causal tile skip)
// ---------------------------------------------------------------------------
__global__ void __launch_bounds__(256) scores_kernel()
{
    int q0 = blockIdx.x * 64;
    int k0 = blockIdx.y * 64;
    if (k0 > q0 + 63) return;
    int bh = blockIdx.z;
    int b = bh >> 4, h = bh & 15;

    __shared__ float Qs[64][65];
    __shared__ float Ks[64][65];
    int tid = threadIdx.x;

    for (int i = tid; i < 64 * 64; i += 256) {
        int r = i >> 6, c = i & 63;
        Qs[r][c] = g_qkv[(size_t)(b * S_ + q0 + r) * (3 * D_) + h * 192 + c];
        Ks[r][c] = g_qkv[(size_t)(b * S_ + k0 + r) * (3 * D_) + h * 192 + 64 + c];
    }
    __syncthreads();

    int ty = tid >> 4, tx = tid & 15;
    float acc[4][4];
#pragma unroll
    for (int i = 0; i < 4; i++)
#pragma unroll
        for (int j = 0; j < 4; j++) acc[i][j] = 0.f;

#pragma unroll 8
    for (int d = 0; d < 64; d++) {
        float a[4], bb[4];
#pragma unroll
        for (int i = 0; i < 4; i++) a[i]  = Qs[ty * 4 + i][d];
#pragma unroll
        for (int j = 0; j < 4; j++) bb[j] = Ks[tx * 4 + j][d];
#pragma unroll
        for (int i = 0; i < 4; i++)
#pragma unroll
            for (int j = 0; j < 4; j++)
                acc[i][j] = fmaf(a[i], bb[j], acc[i][j]);
    }

    const float scale = 0.125f;
#pragma unroll
    for (int i = 0; i < 4; i++) {
        int q = q0 + ty * 4 + i;
#pragma unroll
        for (int j = 0; j < 4; j++) {
            int k = k0 + tx * 4 + j;
            g_scores[((size_t)bh * S_ + q) * S_ + k] = acc[i][j] * scale;
        }
    }
}

// ---------------------------------------------------------------------------
// Causal softmax
// ---------------------------------------------------------------------------
__global__ void __launch_bounds__(256) softmax_kernel()
{
    int row = blockIdx.x;
    int q = row & (S_ - 1);
    float* p = g_scores + (size_t)row * S_;
    int valid = q + 1;
    int tid = threadIdx.x;
    __shared__ float red[256];

    float m = -1e30f;
    for (int c = tid; c < valid; c += 256) m = fmaxf(m, p[c]);
    red[tid] = m; __syncthreads();
    for (int o = 128; o > 0; o >>= 1) {
        if (tid < o) red[tid] = fmaxf(red[tid], red[tid + o]);
        __syncthreads();
    }
    m = red[0]; __syncthreads();

    float s = 0.f;
    for (int c = tid; c < valid; c += 256) {
        float e = __expf(p[c] - m);
        p[c] = e;
        s += e;
    }
    red[tid] = s; __syncthreads();
    for (int o = 128; o > 0; o >>= 1) {
        if (tid < o) red[tid] += red[tid + o];
        __syncthreads();
    }
    float inv = 1.f / red[0];

    for (int c = tid; c < valid; c += 256) p[c] *= inv;
    for (int c = valid + tid; c < S_; c += 256) p[c] = 0.f;
}

// ---------------------------------------------------------------------------
// P @ V (fp32 FFMA, causal chunk skip) -> fp32 g_attn
// ---------------------------------------------------------------------------
__global__ void __launch_bounds__(256) attnout_kernel()
{
    int q0 = blockIdx.x * 64;
    int bh = blockIdx.y;
    int b = bh >> 4, h = bh & 15;

    __shared__ float Ps[64][65];
    __shared__ float Vs[64][65];
    int tid = threadIdx.x;
    int ty = tid >> 4, tx = tid & 15;

    float acc[4][4];
#pragma unroll
    for (int i = 0; i < 4; i++)
#pragma unroll
        for (int j = 0; j < 4; j++) acc[i][j] = 0.f;

    int nChunks = (q0 >> 6) + 1;
    for (int kc = 0; kc < nChunks; kc++) {
        int k0 = kc * 64;
        for (int i = tid; i < 64 * 64; i += 256) {
            int r = i >> 6, c = i & 63;
            Ps[r][c] = g_scores[((size_t)bh * S_ + q0 + r) * S_ + k0 + c];
            Vs[r][c] = g_qkv[(size_t)(b * S_ + k0 + r) * (3 * D_) + h * 192 + 128 + c];
        }
        __syncthreads();

#pragma unroll 8
        for (int kk = 0; kk < 64; kk++) {
            float a[4], bb[4];
#pragma unroll
            for (int i = 0; i < 4; i++) a[i]  = Ps[ty * 4 + i][kk];
#pragma unroll
            for (int j = 0; j < 4; j++) bb[j] = Vs[kk][tx * 4 + j];
#pragma unroll
            for (int i = 0; i < 4; i++)
#pragma unroll
                for (int j = 0; j < 4; j++)
                    acc[i][j] = fmaf(a[i], bb[j], acc[i][j]);
        }
        __syncthreads();
    }

#pragma unroll
    for (int i = 0; i < 4; i++) {
        int q = q0 + ty * 4 + i;
#pragma unroll
        for (int j = 0; j < 4; j++) {
            int d = tx * 4 + j;
            g_attn[(size_t)(b * S_ + q) * D_ + h * 64 + d] = acc[i][j];
        }
    }
}

// ---------------------------------------------------------------------------
// Host launcher
// ---------------------------------------------------------------------------
extern "C" void kernel_launch(void* const* d_in, const int* in_sizes, int n_in,
                              void* d_out, int out_size)
{
    const int*   idx     = (const int*)  d_in[0];
    const float* tok_emb = (const float*)d_in[1];
    const float* pos_emb = (const float*)d_in[2];
    const float* qkv_w   = (const float*)d_in[3];
    const float* proj_w  = (const float*)d_in[4];
    const float* proj_b  = (const float*)d_in[5];
    const float* ln1_s   = (const float*)d_in[6];
    const float* ln1_b   = (const float*)d_in[7];
    const float* fc1_w   = (const float*)d_in[8];
    const float* fc1_b   = (const float*)d_in[9];
    const float* fc2_w   = (const float*)d_in[10];
    const float* fc2_b   = (const float*)d_in[11];
    const float* ln2_s   = (const float*)d_in[12];
    const float* ln2_b   = (const float*)d_in[13];
    const float* lnf_s   = (const float*)d_in[14];
    const float* lnf_b   = (const float*)d_in[15];
    const float* head_w  = (const float*)d_in[16];
    const float* head_b  = (const float*)d_in[17];
    float* out = (float*)d_out;

    float *x, *qkvp, *attnf, *ffhf;
    int8_t *h1, *h2, *at1, *at2, *ff1, *ff2;
    float *sh, *sat, *sff;
    int8_t *wq1, *wq2, *wp1, *wp2, *w11, *w12, *w21, *w22, *wh1, *wh2;
    float *sq, *sp, *s1, *s2, *shd;
    cudaGetSymbolAddress((void**)&x,     g_x);
    cudaGetSymbolAddress((void**)&qkvp,  g_qkv);
    cudaGetSymbolAddress((void**)&attnf, g_attn);
    cudaGetSymbolAddress((void**)&ffhf,  g_ffh);
    cudaGetSymbolAddress((void**)&h1,  g_h1);  cudaGetSymbolAddress((void**)&h2,  g_h2);
    cudaGetSymbolAddress((void**)&at1, g_at1); cudaGetSymbolAddress((void**)&at2, g_at2);
    cudaGetSymbolAddress((void**)&ff1, g_ff1); cudaGetSymbolAddress((void**)&ff2, g_ff2);
    cudaGetSymbolAddress((void**)&sh,  g_sh);  cudaGetSymbolAddress((void**)&sat, g_sat);
    cudaGetSymbolAddress((void**)&sff, g_sff);
    cudaGetSymbolAddress((void**)&wq1, w_qkv1);  cudaGetSymbolAddress((void**)&wq2, w_qkv2);
    cudaGetSymbolAddress((void**)&wp1, w_proj1); cudaGetSymbolAddress((void**)&wp2, w_proj2);
    cudaGetSymbolAddress((void**)&w11, w_fc11);  cudaGetSymbolAddress((void**)&w12, w_fc12);
    cudaGetSymbolAddress((void**)&w21, w_fc21);  cudaGetSymbolAddress((void**)&w22, w_fc22);
    cudaGetSymbolAddress((void**)&wh1, w_hd1);   cudaGetSymbolAddress((void**)&wh2, w_hd2);
    cudaGetSymbolAddress((void**)&sq,  s_qkv);  cudaGetSymbolAddress((void**)&sp, s_proj);
    cudaGetSymbolAddress((void**)&s1,  s_fc1);  cudaGetSymbolAddress((void**)&s2, s_fc2);
    cudaGetSymbolAddress((void**)&shd, s_hd);

    cudaFuncSetAttribute(gemm_i8,
                         cudaFuncAttributeMaxDynamicSharedMemorySize, GEMM_SMEM);

    // quantize all weights (once per call)
    quant_kernel<<<L_ * 3 * D_, 256>>>(qkv_w,  wq1, wq2, sq,  D_);
    quant_kernel<<<L_ * D_, 256>>>(proj_w, wp1, wp2, sp,  D_);
    quant_kernel<<<L_ * FF_, 256>>>(fc1_w,  w11, w12, s1,  D_);
    quant_kernel<<<L_ * D_, 256>>>(fc2_w,  w21, w22, s2,  FF_);
    quant_kernel<<<V_, 256>>>(head_w, wh1, wh2, shd, D_);

    embed_kernel<<<NTOK, 256>>>(idx, tok_emb, pos_emb);

    for (int l = 0; l < L_; l++) {
        ln_q8_kernel<<<NTOK, 256>>>(x, h1, h2, sh, ln1_s + l * D_, ln1_b + l * D_);
        gemm_i8<<<dim3(3 * D_ / 128, NTOK / 128), 512, GEMM_SMEM>>>(
            h1, h2, sh, wq1 + (size_t)l * 3 * D_ * D_, wq2 + (size_t)l * 3 * D_ * D_,
            sq + l * 3 * D_, nullptr, nullptr, qkvp, NTOK, 3 * D_, D_, 0);
        scores_kernel<<<dim3(S_ / 64, S_ / 64, B_ * H_), 256>>>();
        softmax_kernel<<<B_ * H_ * S_, 256>>>();
        attnout_kernel<<<dim3(S_ / 64, B_ * H_), 256>>>();
        quant_kernel<<<NTOK, 256>>>(attnf, at1, at2, sat, D_);
        gemm_i8<<<dim3(D_ / 128, NTOK / 128), 512, GEMM_SMEM>>>(
            at1, at2, sat, wp1 + (size_t)l * D_ * D_, wp2 + (size_t)l * D_ * D_,
            sp + l * D_, proj_b + l * D_, x, x, NTOK, D_, D_, 0);
        ln_q8_kernel<<<NTOK, 256>>>(x, h1, h2, sh, ln2_s + l * D_, ln2_b + l * D_);
        gemm_i8<<<dim3(FF_ / 128, NTOK / 128), 512, GEMM_SMEM>>>(
            h1, h2, sh, w11 + (size_t)l * FF_ * D_, w12 + (size_t)l * FF_ * D_,
            s1 + l * FF_, fc1_b + l * FF_, nullptr, ffhf, NTOK, FF_, D_, 1);
        quant_kernel<<<NTOK, 256>>>(ffhf, ff1, ff2, sff, FF_);
        gemm_i8<<<dim3(D_ / 128, NTOK / 128), 512, GEMM_SMEM>>>(
            ff1, ff2, sff, w21 + (size_t)l * D_ * FF_, w22 + (size_t)l * D_ * FF_,
            s2 + l * D_, fc2_b + l * D_, x, x, NTOK, D_, FF_, 0);
    }

    ln_q8_kernel<<<NTOK, 256>>>(x, h1, h2, sh, lnf_s, lnf_b);
    gemm_i8<<<dim3((V_ + 127) / 128, NTOK / 128), 512, GEMM_SMEM>>>(
        h1, h2, sh, wh1, wh2, shd, head_b, nullptr, out, NTOK, V_, D_, 0);
}